// round 1
// baseline (speedup 1.0000x reference)
#include <cuda_runtime.h>
#include <cuda_bf16.h>

#define BB 4
#define CC 64
#define HH 128
#define WW 128
#define HWW (HH*WW)
#define NPIX (BB*HH*WW)
#define OC 18

// Scratch (allocation-free rule: device globals)
__device__ float g_xt[BB*HH*WW*CC];     // NHWC transposed input, 16.8 MB
__device__ float g_off[NPIX*OC];        // offsets per pixel [18], 4.7 MB
__device__ float g_mean[CC];
__device__ float g_istd[CC];

// ---------------------------------------------------------------------------
// Kernel 0: NCHW -> NHWC transpose (tiled via shared, conflict-free)
// ---------------------------------------------------------------------------
__global__ void k_transpose(const float* __restrict__ x) {
    __shared__ float s[64][33];
    int w0 = blockIdx.x * 32;
    int h  = blockIdx.y;
    int b  = blockIdx.z;
    int tx = threadIdx.x, ty = threadIdx.y;
    #pragma unroll
    for (int c = ty; c < 64; c += 8)
        s[c][tx] = x[((b*64 + c)*HH + h)*WW + w0 + tx];
    __syncthreads();
    int pixbase = (b*HH + h)*WW + w0;
    #pragma unroll
    for (int wi = ty; wi < 32; wi += 8) {
        g_xt[(pixbase + wi)*64 + tx]      = s[tx][wi];
        g_xt[(pixbase + wi)*64 + 32 + tx] = s[32 + tx][wi];
    }
}

// ---------------------------------------------------------------------------
// Kernel 1: offset conv 3x3, 64 -> 18 channels, pad 1.
// Thread = pixel. Weights in shared as [k][och][c] for LDS.128 inner reads.
// ---------------------------------------------------------------------------
__global__ __launch_bounds__(256) void k_offconv(const float* __restrict__ ow,
                                                 const float* __restrict__ ob) {
    __shared__ float sW[9 * OC * 64];   // 41472 B
    int tid = threadIdx.x;
    for (int i = tid; i < 9 * OC * 64; i += 256) {
        int k = i / (OC * 64);
        int r = i % (OC * 64);
        int och = r / 64;
        int c = r % 64;
        sW[i] = ow[(och * 64 + c) * 9 + k];     // src layout [och][c][ki][kj]
    }
    __syncthreads();

    int pid = blockIdx.x * 256 + tid;
    int b = pid / HWW;
    int rem = pid % HWW;
    int h = rem / WW;
    int w = rem % WW;

    float acc[OC];
    #pragma unroll
    for (int o = 0; o < OC; o++) acc[o] = __ldg(ob + o);

    #pragma unroll
    for (int ki = 0; ki < 3; ki++) {
        int y = h - 1 + ki;
        if (y < 0 || y >= HH) continue;
        #pragma unroll
        for (int kj = 0; kj < 3; kj++) {
            int xx = w - 1 + kj;
            if (xx < 0 || xx >= WW) continue;
            const float* px = g_xt + ((b*HH + y)*WW + xx) * 64;
            const float* wk = sW + (ki*3 + kj) * OC * 64;
            #pragma unroll 1
            for (int c0 = 0; c0 < 64; c0 += 4) {
                float4 v = *(const float4*)(px + c0);
                #pragma unroll
                for (int o = 0; o < OC; o++) {
                    float4 wv = *(const float4*)(wk + o*64 + c0);
                    acc[o] += v.x*wv.x + v.y*wv.y + v.z*wv.z + v.w*wv.w;
                }
            }
        }
    }
    float* op = g_off + pid * OC;
    #pragma unroll
    for (int o = 0; o < OC; o++) op[o] = acc[o];
}

// ---------------------------------------------------------------------------
// Kernel 2: deformable sampling + DCN conv. Thread = pixel, acc[64] in regs.
// Weights in dynamic shared as [k][o][c] (147456 B) -> broadcast LDS.128.
// Writes NCHW conv output directly into d_out (pre-BN).
// ---------------------------------------------------------------------------
__global__ __launch_bounds__(256) void k_dcn(const float* __restrict__ dw,
                                             float* __restrict__ out) {
    extern __shared__ float sW[];       // 9*64*64 floats
    int tid = threadIdx.x;
    for (int i = tid; i < 9 * 64 * 64; i += 256) {
        int k = i / 4096;
        int r = i % 4096;
        int o = r / 64;
        int c = r % 64;
        sW[i] = dw[(o * 64 + c) * 9 + k];       // src layout [o][c][ki][kj]
    }
    __syncthreads();

    int pid = blockIdx.x * 256 + tid;
    int b = pid / HWW;
    int rem = pid % HWW;
    int h = rem / WW;
    int w = rem % WW;

    const float* op = g_off + pid * OC;

    float acc[64];
    #pragma unroll
    for (int o = 0; o < 64; o++) acc[o] = 0.f;

    #pragma unroll 1
    for (int k = 0; k < 9; k++) {
        int ki = k / 3, kj = k % 3;
        float py = op[2*k]     + (float)(h - 1 + ki);
        float px = op[2*k + 1] + (float)(w - 1 + kj);
        float y0f = floorf(py), x0f = floorf(px);
        float wy = py - y0f, wx = px - x0f;
        int y0 = (int)y0f, x0 = (int)x0f;
        // corner validity (match reference: corner counted only if fully in range)
        bool vy0 = (y0 >= 0)  && (y0 <= HH - 1);
        bool vy1 = (y0 >= -1) && (y0 <= HH - 2);
        bool vx0 = (x0 >= 0)  && (x0 <= WW - 1);
        bool vx1 = (x0 >= -1) && (x0 <= WW - 2);
        float w00 = (1.f - wy) * (1.f - wx) * ((vy0 && vx0) ? 1.f : 0.f);
        float w01 = (1.f - wy) * wx         * ((vy0 && vx1) ? 1.f : 0.f);
        float w10 = wy * (1.f - wx)         * ((vy1 && vx0) ? 1.f : 0.f);
        float w11 = wy * wx                 * ((vy1 && vx1) ? 1.f : 0.f);
        int y0c = min(max(y0, 0), HH - 1), y1c = min(max(y0 + 1, 0), HH - 1);
        int x0c = min(max(x0, 0), WW - 1), x1c = min(max(x0 + 1, 0), WW - 1);
        const float* p00 = g_xt + ((b*HH + y0c)*WW + x0c) * 64;
        const float* p01 = g_xt + ((b*HH + y0c)*WW + x1c) * 64;
        const float* p10 = g_xt + ((b*HH + y1c)*WW + x0c) * 64;
        const float* p11 = g_xt + ((b*HH + y1c)*WW + x1c) * 64;
        const float* wk = sW + k * 4096;
        #pragma unroll 1
        for (int c0 = 0; c0 < 64; c0 += 4) {
            float4 a00 = *(const float4*)(p00 + c0);
            float4 a01 = *(const float4*)(p01 + c0);
            float4 a10 = *(const float4*)(p10 + c0);
            float4 a11 = *(const float4*)(p11 + c0);
            float4 s;
            s.x = w00*a00.x + w01*a01.x + w10*a10.x + w11*a11.x;
            s.y = w00*a00.y + w01*a01.y + w10*a10.y + w11*a11.y;
            s.z = w00*a00.z + w01*a01.z + w10*a10.z + w11*a11.z;
            s.w = w00*a00.w + w01*a01.w + w10*a10.w + w11*a11.w;
            #pragma unroll
            for (int o = 0; o < 64; o++) {
                float4 wv = *(const float4*)(wk + o*64 + c0);
                acc[o] += s.x*wv.x + s.y*wv.y + s.z*wv.z + s.w*wv.w;
            }
        }
    }
    // NCHW write: coalesced per-o across the warp (rem consecutive)
    int obase = b * 64 * HWW + rem;
    #pragma unroll
    for (int o = 0; o < 64; o++) out[obase + o * HWW] = acc[o];
}

// ---------------------------------------------------------------------------
// Kernel 3: per-channel mean/var over (B,H,W). One block per channel.
// ---------------------------------------------------------------------------
__global__ __launch_bounds__(256) void k_bnstats(const float* __restrict__ out) {
    int o = blockIdx.x;
    __shared__ float ssum[256];
    __shared__ float ssq[256];
    float s = 0.f, q = 0.f;
    for (int i = threadIdx.x; i < BB * HWW; i += 256) {
        int b = i / HWW, r = i % HWW;
        float v = out[(b * 64 + o) * HWW + r];
        s += v;
        q += v * v;
    }
    ssum[threadIdx.x] = s;
    ssq[threadIdx.x] = q;
    __syncthreads();
    for (int st = 128; st > 0; st >>= 1) {
        if (threadIdx.x < st) {
            ssum[threadIdx.x] += ssum[threadIdx.x + st];
            ssq[threadIdx.x]  += ssq[threadIdx.x + st];
        }
        __syncthreads();
    }
    if (threadIdx.x == 0) {
        float inv_n = 1.f / (float)(BB * HWW);
        float mean = ssum[0] * inv_n;
        float var  = ssq[0] * inv_n - mean * mean;
        g_mean[o] = mean;
        g_istd[o] = rsqrtf(var + 1e-5f);
    }
}

// ---------------------------------------------------------------------------
// Kernel 4: normalize + affine + ReLU, in place on d_out. float4 vectorized.
// ---------------------------------------------------------------------------
__global__ __launch_bounds__(256) void k_bnapply(float* __restrict__ out,
                                                 const float* __restrict__ gamma,
                                                 const float* __restrict__ beta) {
    int i4 = blockIdx.x * 256 + threadIdx.x;        // float4 index
    int i = i4 * 4;
    int o = (i / HWW) % 64;                          // HW divisible by 4 -> same o
    float scale = g_istd[o] * __ldg(gamma + o);
    float shift = __ldg(beta + o) - g_mean[o] * scale;
    float4 v = *((float4*)out + i4);
    v.x = fmaxf(v.x * scale + shift, 0.f);
    v.y = fmaxf(v.y * scale + shift, 0.f);
    v.z = fmaxf(v.z * scale + shift, 0.f);
    v.w = fmaxf(v.w * scale + shift, 0.f);
    *((float4*)out + i4) = v;
}

// ---------------------------------------------------------------------------
extern "C" void kernel_launch(void* const* d_in, const int* in_sizes, int n_in,
                              void* d_out, int out_size) {
    const float* x     = (const float*)d_in[0];
    const float* ow    = (const float*)d_in[1];
    const float* ob    = (const float*)d_in[2];
    const float* dw    = (const float*)d_in[3];
    const float* gamma = (const float*)d_in[4];
    const float* beta  = (const float*)d_in[5];
    float* out = (float*)d_out;

    dim3 tb(32, 8);
    k_transpose<<<dim3(WW / 32, HH, BB), tb>>>(x);

    k_offconv<<<NPIX / 256, 256>>>(ow, ob);

    const int dcn_smem = 9 * 64 * 64 * (int)sizeof(float);   // 147456 B
    cudaFuncSetAttribute(k_dcn, cudaFuncAttributeMaxDynamicSharedMemorySize, dcn_smem);
    k_dcn<<<NPIX / 256, 256, dcn_smem>>>(dw, out);

    k_bnstats<<<64, 256>>>(out);

    k_bnapply<<<(BB * 64 * HWW / 4) / 256, 256>>>(out, gamma, beta);
}